// round 2
// baseline (speedup 1.0000x reference)
#include <cuda_runtime.h>

#define B_ 2
#define N_ 4096
#define M_ 4096
#define K_ 2048
#define NN 8192          // B_*N_ flattened points
#define KTOP 50

static __device__ unsigned g_min_pg[B_*N_];   // min over gt for each pred
static __device__ unsigned g_min_gp[B_*M_];   // min over pred for each gt
static __device__ unsigned g_min_cov[B_*K_];  // min over pred for each partial
static __device__ double   g_acc[8];          // 0:cham1 1:cham2 2:cov 3:emd 4:unif 5:spread 6:rep
static __device__ float4   g_pts4[NN];        // packed pred points for uniformity
static __device__ float    g_sortP[3*NN];
static __device__ float    g_sortG[3*NN];

// ---------------------------------------------------------------- helpers
__device__ __forceinline__ void block_add_to_acc(float v, int slot) {
    for (int o = 16; o; o >>= 1) v += __shfl_xor_sync(0xFFFFFFFFu, v, o);
    __shared__ float sw[32];
    int lane = threadIdx.x & 31, wid = threadIdx.x >> 5;
    if (lane == 0) sw[wid] = v;
    __syncthreads();
    if (threadIdx.x == 0) {
        float s = 0.f;
        int nw = (blockDim.x + 31) >> 5;
        for (int w = 0; w < nw; w++) s += sw[w];
        atomicAdd(&g_acc[slot], (double)s);
    }
}

__device__ __forceinline__ unsigned* min_sel(int which) {
    return which == 0 ? g_min_pg : (which == 1 ? g_min_gp : g_min_cov);
}

// ---------------------------------------------------------------- init
__global__ void init_kernel() {
    int i = blockIdx.x * 256 + threadIdx.x;
    if (i < B_*N_) g_min_pg[i]  = 0x7F800000u;
    if (i < B_*M_) g_min_gp[i]  = 0x7F800000u;
    if (i < B_*K_) g_min_cov[i] = 0x7F800000u;
    if (i < 8)     g_acc[i] = 0.0;
}

__global__ void pack_kernel(const float* __restrict__ pred) {
    int i = blockIdx.x * 256 + threadIdx.x;
    if (i < NN) g_pts4[i] = make_float4(pred[3*i], pred[3*i+1], pred[3*i+2], 0.f);
}

// ---------------------------------------------------------------- row-min pairwise sq dist
// Each thread owns one A point; scans a chunk of B points staged in smem.
__global__ void rowmin_kernel(const float* __restrict__ A, const float* __restrict__ Bp,
                              int nA, int nB, int chunk, int which) {
    __shared__ float sb[384];
    int b = blockIdx.z;
    const float* Ab = A  + (size_t)b * nA * 3;
    const float* Bb = Bp + ((size_t)b * nB + (size_t)blockIdx.y * chunk) * 3;
    int i = blockIdx.x * 128 + threadIdx.x;
    float ax = Ab[3*i], ay = Ab[3*i+1], az = Ab[3*i+2];
    float best = __int_as_float(0x7F800000);
    for (int t = 0; t < chunk; t += 128) {
        __syncthreads();
        const float* src = Bb + 3*t;
        sb[threadIdx.x]       = src[threadIdx.x];
        sb[threadIdx.x + 128] = src[threadIdx.x + 128];
        sb[threadIdx.x + 256] = src[threadIdx.x + 256];
        __syncthreads();
#pragma unroll 16
        for (int j = 0; j < 128; j++) {
            float dx = ax - sb[3*j], dy = ay - sb[3*j+1], dz = az - sb[3*j+2];
            float dd = fmaf(dx, dx, fmaf(dy, dy, dz*dz));
            best = fminf(best, dd);
        }
    }
    atomicMin(&min_sel(which)[b*nA + i], __float_as_uint(best));
}

__global__ void summin_kernel(int which, int n, int do_sqrt, int slot) {
    int i = blockIdx.x * 256 + threadIdx.x;
    float v = 0.f;
    if (i < n) {
        v = __uint_as_float(min_sel(which)[i]);
        if (do_sqrt) v = sqrtf(v);
    }
    block_add_to_acc(v, slot);
}

// ---------------------------------------------------------------- EMD: bitonic column sort
__global__ void emd_sort_kernel(const float* __restrict__ pred, const float* __restrict__ gt) {
    __shared__ float a[NN];
    int which = blockIdx.x;           // 0..5
    int c = which % 3;
    const float* src = (which < 3) ? pred : gt;
    float* dst = (which < 3) ? (g_sortP + c*NN) : (g_sortG + c*NN);
    int tid = threadIdx.x;
    for (int i = tid; i < NN; i += 1024) a[i] = src[3*i + c];
    __syncthreads();
    for (int k = 2; k <= NN; k <<= 1)
        for (int j = k >> 1; j > 0; j >>= 1) {
            for (int i = tid; i < NN; i += 1024) {
                int ixj = i ^ j;
                if (ixj > i) {
                    float x = a[i], y = a[ixj];
                    bool up = ((i & k) == 0);
                    if ((x > y) == up) { a[i] = y; a[ixj] = x; }
                }
            }
            __syncthreads();
        }
    for (int i = tid; i < NN; i += 1024) dst[i] = a[i];
}

__global__ void emd_diff_kernel() {
    int i = blockIdx.x * 256 + threadIdx.x;
    float v = 0.f;
    if (i < 3*NN) { float d = g_sortP[i] - g_sortG[i]; v = d*d; }
    block_add_to_acc(v, 3);
}

// ---------------------------------------------------------------- uniformity: per-row 50-NN std
// Block handles 32 rows; distances to all 8192 points kept in registers (32/thread).
// Exact top-50 via exponent-bucket histogram -> candidate gather -> warp extraction.
__global__ void __launch_bounds__(256) uniformity_kernel() {
    __shared__ float    s_buf[2048];
    __shared__ unsigned s_hist[256];
    __shared__ unsigned s_cnt;
    __shared__ unsigned s_E;
    int tid = threadIdx.x, lane = tid & 31, wid = tid >> 5;
    double rowacc = 0.0;   // meaningful only on tid==0

    for (int r = 0; r < 32; r++) {
        int row = blockIdx.x * 32 + r;
        float4 p = g_pts4[row];
        s_hist[tid & 255] = 0;
        if (tid == 0) s_cnt = 0;
        __syncthreads();

        float d[32];
#pragma unroll
        for (int k = 0; k < 32; k++) {
            float4 q = g_pts4[k*256 + tid];
            float dx = p.x - q.x, dy = p.y - q.y, dz = p.z - q.z;
            d[k] = fmaf(dx, dx, fmaf(dy, dy, dz*dz));
        }
        // exponent-bucket histogram with warp aggregation
#pragma unroll
        for (int k = 0; k < 32; k++) {
            unsigned bin = __float_as_uint(d[k]) >> 23;
            unsigned mask = __match_any_sync(0xFFFFFFFFu, bin);
            int leader = __ffs(mask) - 1;
            if (lane == leader) atomicAdd(&s_hist[bin], (unsigned)__popc(mask));
        }
        __syncthreads();
        // warp 0: find smallest bucket E with cumulative count >= KTOP
        if (wid == 0) {
            unsigned v[8], loc = 0;
#pragma unroll
            for (int b2 = 0; b2 < 8; b2++) { v[b2] = s_hist[lane*8 + b2]; loc += v[b2]; }
            unsigned pre = loc;
            for (int o = 1; o < 32; o <<= 1) {
                unsigned t2 = __shfl_up_sync(0xFFFFFFFFu, pre, o);
                if (lane >= o) pre += t2;
            }
            unsigned cum = pre - loc;
            int myE = 256;
#pragma unroll
            for (int b2 = 0; b2 < 8; b2++) {
                cum += v[b2];
                if ((int)cum >= KTOP && myE == 256) myE = lane*8 + b2;
            }
            for (int o = 16; o; o >>= 1) {
                int t3 = __shfl_xor_sync(0xFFFFFFFFu, myE, o);
                myE = min(myE, t3);
            }
            if (lane == 0) s_E = (unsigned)myE;
        }
        __syncthreads();
        unsigned E = s_E;
        // gather candidates
#pragma unroll
        for (int k = 0; k < 32; k++) {
            unsigned bin = __float_as_uint(d[k]) >> 23;
            if (bin <= E) {
                unsigned pos = atomicAdd(&s_cnt, 1u);
                if (pos < 2048) s_buf[pos] = d[k];
            }
        }
        __syncthreads();
        // warp 0: extract KTOP smallest; skip rank 0 (self distance 0)
        if (wid == 0) {
            int c = (int)min(s_cnt, 2048u);
            volatile float* vb = s_buf;
            double s1 = 0.0, s2 = 0.0;
            for (int it = 0; it < KTOP; it++) {
                float best = __int_as_float(0x7F800000); int bi = -1;
                for (int j = lane; j < c; j += 32) {
                    float vv = vb[j];
                    if (vv < best) { best = vv; bi = j; }
                }
                for (int o = 16; o; o >>= 1) {
                    float ov = __shfl_xor_sync(0xFFFFFFFFu, best, o);
                    int   oi = __shfl_xor_sync(0xFFFFFFFFu, bi, o);
                    if (ov < best || (ov == best && oi >= 0 && (bi < 0 || oi < bi))) {
                        best = ov; bi = oi;
                    }
                }
                if (lane == 0 && bi >= 0) vb[bi] = __int_as_float(0x7F800000);
                __syncwarp();
                if (it >= 1 && lane == 0) {
                    s1 += (double)sqrtf(best);   // distance
                    s2 += (double)best;          // distance^2 == d2
                }
            }
            if (lane == 0) {
                double mean = s1 / 49.0;
                double var = (s2 - 49.0*mean*mean) / 48.0;
                if (var < 0.0) var = 0.0;
                rowacc += sqrt(var);
            }
        }
        __syncthreads();
    }
    if (tid == 0) atomicAdd(&g_acc[4], rowacc);
}

// ---------------------------------------------------------------- spread
__global__ void spread_kernel(const float* __restrict__ pred) {
    int b = blockIdx.x / 3, c = blockIdx.x % 3;
    const float* p = pred + (size_t)b * N_ * 3 + c;
    double s1 = 0.0, s2 = 0.0;
    for (int i = threadIdx.x; i < N_; i += 256) {
        double x = (double)p[3*i];
        s1 += x; s2 += x*x;
    }
    for (int o = 16; o; o >>= 1) {
        s1 += __shfl_xor_sync(0xFFFFFFFFu, s1, o);
        s2 += __shfl_xor_sync(0xFFFFFFFFu, s2, o);
    }
    __shared__ double sw1[8], sw2[8];
    int lane = threadIdx.x & 31, wid = threadIdx.x >> 5;
    if (lane == 0) { sw1[wid] = s1; sw2[wid] = s2; }
    __syncthreads();
    if (threadIdx.x == 0) {
        double a = 0, bb = 0;
        for (int w = 0; w < 8; w++) { a += sw1[w]; bb += sw2[w]; }
        double mean = a / (double)N_;
        double var = (bb - (double)N_ * mean * mean) / (double)(N_ - 1);
        if (var < 0.0) var = 0.0;
        atomicAdd(&g_acc[5], sqrt(var));
    }
}

// ---------------------------------------------------------------- repulsion
// NOTE: sample_idx arrives as int32 (JAX x64 disabled downcasts astype(int64)).
__global__ void repulsion_kernel(const float* __restrict__ pred,
                                 const int* __restrict__ sidx) {
    __shared__ float sp[200*3];
    int tid = threadIdx.x;
    for (int s = tid; s < 200; s += 256) {
        int b = s / 100, k = s % 100;
        int idx = sidx[k];
        if (idx < 0) idx = 0;
        if (idx >= N_) idx = N_ - 1;
        const float* src = pred + ((size_t)b * N_ + (size_t)idx) * 3;
        sp[3*s] = src[0]; sp[3*s+1] = src[1]; sp[3*s+2] = src[2];
    }
    __syncthreads();
    float sum = 0.f;
    for (int t = tid; t < 2*100*100; t += 256) {
        int b = t / 10000, rem = t % 10000, i = rem / 100, j = rem % 100;
        if (i != j) {
            const float* pi = &sp[(b*100 + i)*3];
            const float* pj = &sp[(b*100 + j)*3];
            float dx = pi[0]-pj[0], dy = pi[1]-pj[1], dz = pi[2]-pj[2];
            float dd = fmaf(dx, dx, fmaf(dy, dy, dz*dz));
            float rr = 0.01f - sqrtf(dd);
            if (rr > 0.f) sum += rr;
        }
    }
    block_add_to_acc(sum, 6);
}

// ---------------------------------------------------------------- finalize
__global__ void final_kernel(float* out) {
    double cham   = g_acc[0] / (double)(B_*N_) + g_acc[1] / (double)(B_*M_);
    double emd    = g_acc[3] / (double)(NN*3) * 0.1;
    double cov    = g_acc[2] / (double)(B_*K_) * 5.0;
    double unif   = g_acc[4] / (double)NN * 2.0;
    double sstd   = g_acc[5] / 6.0;
    double spread = 0.5 - sstd;
    spread = (spread > 0.0) ? spread * 10.0 : 0.0;
    double rep    = g_acc[6] / (double)(B_*100*100) * 5.0;
    out[0] = (float)(cham + emd + cov + unif + spread + rep);
}

// ---------------------------------------------------------------- launch
extern "C" void kernel_launch(void* const* d_in, const int* in_sizes, int n_in,
                              void* d_out, int out_size) {
    const float* pred    = (const float*)d_in[0];
    const float* gt      = (const float*)d_in[1];
    const float* partial = (const float*)d_in[2];
    const int*   sidx    = (const int*)d_in[3];
    float* out = (float*)d_out;

    init_kernel<<<32, 256>>>();
    pack_kernel<<<32, 256>>>(pred);

    // chamfer pred->gt and gt->pred, coverage partial->pred
    rowmin_kernel<<<dim3(N_/128, 4, B_), 128>>>(pred, gt,   N_, M_, M_/4, 0);
    rowmin_kernel<<<dim3(M_/128, 4, B_), 128>>>(gt,   pred, M_, N_, N_/4, 1);
    rowmin_kernel<<<dim3(K_/128, 8, B_), 128>>>(partial, pred, K_, N_, N_/8, 2);

    summin_kernel<<<(B_*N_+255)/256, 256>>>(0, B_*N_, 0, 0);
    summin_kernel<<<(B_*M_+255)/256, 256>>>(1, B_*M_, 0, 1);
    summin_kernel<<<(B_*K_+255)/256, 256>>>(2, B_*K_, 1, 2);

    emd_sort_kernel<<<6, 1024>>>(pred, gt);
    emd_diff_kernel<<<(3*NN+255)/256, 256>>>();

    uniformity_kernel<<<NN/32, 256>>>();

    spread_kernel<<<6, 256>>>(pred);
    repulsion_kernel<<<1, 256>>>(pred, sidx);

    final_kernel<<<1, 1>>>(out);
}

// round 4
// speedup vs baseline: 3.5356x; 3.5356x over previous
#include <cuda_runtime.h>

#define B_ 2
#define N_ 4096
#define M_ 4096
#define K_ 2048
#define NN 8192          // B_*N_ flattened points
#define KTOP 50
#define CAND_CAP 3072

static __device__ unsigned g_min_pg[B_*N_];   // min over gt for each pred
static __device__ unsigned g_min_gp[B_*M_];   // min over pred for each gt
static __device__ unsigned g_min_cov[B_*K_];  // min over pred for each partial
static __device__ double   g_acc[8];          // 0:cham1 1:cham2 2:cov 3:emd 4:unif 5:spread 6:rep
static __device__ float4   g_pts4[NN];        // packed pred points for uniformity
static __device__ float    g_sortP[3*NN];
static __device__ float    g_sortG[3*NN];

// ---------------------------------------------------------------- helpers
__device__ __forceinline__ void block_add_to_acc(float v, int slot) {
    for (int o = 16; o; o >>= 1) v += __shfl_xor_sync(0xFFFFFFFFu, v, o);
    __shared__ float sw[32];
    int lane = threadIdx.x & 31, wid = threadIdx.x >> 5;
    if (lane == 0) sw[wid] = v;
    __syncthreads();
    if (threadIdx.x == 0) {
        float s = 0.f;
        int nw = (blockDim.x + 31) >> 5;
        for (int w = 0; w < nw; w++) s += sw[w];
        atomicAdd(&g_acc[slot], (double)s);
    }
}

__device__ __forceinline__ unsigned* min_sel(int which) {
    return which == 0 ? g_min_pg : (which == 1 ? g_min_gp : g_min_cov);
}

// ---------------------------------------------------------------- init
__global__ void init_kernel() {
    int i = blockIdx.x * 256 + threadIdx.x;
    if (i < B_*N_) g_min_pg[i]  = 0x7F800000u;
    if (i < B_*M_) g_min_gp[i]  = 0x7F800000u;
    if (i < B_*K_) g_min_cov[i] = 0x7F800000u;
    if (i < 8)     g_acc[i] = 0.0;
}

__global__ void pack_kernel(const float* __restrict__ pred) {
    int i = blockIdx.x * 256 + threadIdx.x;
    if (i < NN) g_pts4[i] = make_float4(pred[3*i], pred[3*i+1], pred[3*i+2], 0.f);
}

// ---------------------------------------------------------------- row-min pairwise sq dist
// Each thread owns one A point; scans a chunk of B points staged in smem.
// Two independent min accumulators break the FMNMX dependency chain.
__global__ void rowmin_kernel(const float* __restrict__ A, const float* __restrict__ Bp,
                              int nA, int nB, int chunk, int which) {
    __shared__ float sb[384];
    int b = blockIdx.z;
    const float* Ab = A  + (size_t)b * nA * 3;
    const float* Bb = Bp + ((size_t)b * nB + (size_t)blockIdx.y * chunk) * 3;
    int i = blockIdx.x * 128 + threadIdx.x;
    float ax = Ab[3*i], ay = Ab[3*i+1], az = Ab[3*i+2];
    float best0 = __int_as_float(0x7F800000);
    float best1 = best0;
    for (int t = 0; t < chunk; t += 128) {
        __syncthreads();
        const float* src = Bb + 3*t;
        sb[threadIdx.x]       = src[threadIdx.x];
        sb[threadIdx.x + 128] = src[threadIdx.x + 128];
        sb[threadIdx.x + 256] = src[threadIdx.x + 256];
        __syncthreads();
#pragma unroll 16
        for (int j = 0; j < 128; j += 2) {
            float dx0 = ax - sb[3*j],   dy0 = ay - sb[3*j+1], dz0 = az - sb[3*j+2];
            float dx1 = ax - sb[3*j+3], dy1 = ay - sb[3*j+4], dz1 = az - sb[3*j+5];
            float dd0 = fmaf(dx0, dx0, fmaf(dy0, dy0, dz0*dz0));
            float dd1 = fmaf(dx1, dx1, fmaf(dy1, dy1, dz1*dz1));
            best0 = fminf(best0, dd0);
            best1 = fminf(best1, dd1);
        }
    }
    float best = fminf(best0, best1);
    atomicMin(&min_sel(which)[b*nA + i], __float_as_uint(best));
}

__global__ void summin_kernel(int which, int n, int do_sqrt, int slot) {
    int i = blockIdx.x * 256 + threadIdx.x;
    float v = 0.f;
    if (i < n) {
        v = __uint_as_float(min_sel(which)[i]);
        if (do_sqrt) v = sqrtf(v);
    }
    block_add_to_acc(v, slot);
}

// ---------------------------------------------------------------- EMD: bitonic column sort
__global__ void emd_sort_kernel(const float* __restrict__ pred, const float* __restrict__ gt) {
    __shared__ float a[NN];
    int which = blockIdx.x;           // 0..5
    int c = which % 3;
    const float* src = (which < 3) ? pred : gt;
    float* dst = (which < 3) ? (g_sortP + c*NN) : (g_sortG + c*NN);
    int tid = threadIdx.x;
    for (int i = tid; i < NN; i += 1024) a[i] = src[3*i + c];
    __syncthreads();
    for (int k = 2; k <= NN; k <<= 1)
        for (int j = k >> 1; j > 0; j >>= 1) {
            for (int i = tid; i < NN; i += 1024) {
                int ixj = i ^ j;
                if (ixj > i) {
                    float x = a[i], y = a[ixj];
                    bool up = ((i & k) == 0);
                    if ((x > y) == up) { a[i] = y; a[ixj] = x; }
                }
            }
            __syncthreads();
        }
    for (int i = tid; i < NN; i += 1024) dst[i] = a[i];
}

__global__ void emd_diff_kernel() {
    int i = blockIdx.x * 256 + threadIdx.x;
    float v = 0.f;
    if (i < 3*NN) { float d = g_sortP[i] - g_sortG[i]; v = d*d; }
    block_add_to_acc(v, 3);
}

// ---------------------------------------------------------------- uniformity: per-row 50-NN std
// Block handles 32 rows; distances to all 8192 points kept in registers (32/thread).
// Exact top-50: exponent-bucket histogram -> candidate gather -> PARALLEL rank-by-count.
__global__ void __launch_bounds__(256) uniformity_kernel() {
    __shared__ float    s_buf[CAND_CAP];
    __shared__ unsigned s_hist[256];
    __shared__ unsigned s_cnt;
    __shared__ unsigned s_E;
    __shared__ float    s_r1[8], s_r2[8];
    int tid = threadIdx.x, lane = tid & 31, wid = tid >> 5;
    double rowacc = 0.0;   // meaningful only on tid==0

    for (int r = 0; r < 32; r++) {
        int row = blockIdx.x * 32 + r;
        float4 p = g_pts4[row];
        s_hist[tid] = 0;
        if (tid == 0) s_cnt = 0;
        __syncthreads();

        float d[32];
#pragma unroll
        for (int k = 0; k < 32; k++) {
            float4 q = g_pts4[k*256 + tid];
            float dx = p.x - q.x, dy = p.y - q.y, dz = p.z - q.z;
            d[k] = fmaf(dx, dx, fmaf(dy, dy, dz*dz));
        }
        // exponent-bucket histogram with warp aggregation
#pragma unroll
        for (int k = 0; k < 32; k++) {
            unsigned bin = __float_as_uint(d[k]) >> 23;
            unsigned mask = __match_any_sync(0xFFFFFFFFu, bin);
            int leader = __ffs(mask) - 1;
            if (lane == leader) atomicAdd(&s_hist[bin], (unsigned)__popc(mask));
        }
        __syncthreads();
        // warp 0: find smallest bucket E with cumulative count >= KTOP
        if (wid == 0) {
            unsigned v[8], loc = 0;
#pragma unroll
            for (int b2 = 0; b2 < 8; b2++) { v[b2] = s_hist[lane*8 + b2]; loc += v[b2]; }
            unsigned pre = loc;
            for (int o = 1; o < 32; o <<= 1) {
                unsigned t2 = __shfl_up_sync(0xFFFFFFFFu, pre, o);
                if (lane >= o) pre += t2;
            }
            unsigned cum = pre - loc;
            int myE = 256;
#pragma unroll
            for (int b2 = 0; b2 < 8; b2++) {
                cum += v[b2];
                if ((int)cum >= KTOP && myE == 256) myE = lane*8 + b2;
            }
            for (int o = 16; o; o >>= 1) {
                int t3 = __shfl_xor_sync(0xFFFFFFFFu, myE, o);
                myE = min(myE, t3);
            }
            if (lane == 0) s_E = (unsigned)myE;
        }
        __syncthreads();
        unsigned E = s_E;
        // gather candidates
#pragma unroll
        for (int k = 0; k < 32; k++) {
            unsigned bin = __float_as_uint(d[k]) >> 23;
            if (bin <= E) {
                unsigned pos = atomicAdd(&s_cnt, 1u);
                if (pos < CAND_CAP) s_buf[pos] = d[k];
            }
        }
        __syncthreads();
        // parallel exact selection: rank each candidate by counting
        int c = (int)min(s_cnt, (unsigned)CAND_CAP);
        float t1 = 0.f, t2 = 0.f;
        for (int j = tid; j < c; j += 256) {
            float v = s_buf[j];
            int rank = 0;
            for (int k = 0; k < c; k++) {
                float w = s_buf[k];
                rank += (w < v) || (w == v && k < j);
            }
            if (rank >= 1 && rank < KTOP) { t1 += sqrtf(v); t2 += v; }
        }
        // block reduce (t1, t2)
        for (int o = 16; o; o >>= 1) {
            t1 += __shfl_xor_sync(0xFFFFFFFFu, t1, o);
            t2 += __shfl_xor_sync(0xFFFFFFFFu, t2, o);
        }
        if (lane == 0) { s_r1[wid] = t1; s_r2[wid] = t2; }
        __syncthreads();
        if (tid == 0) {
            double s1 = 0.0, s2 = 0.0;
            for (int w = 0; w < 8; w++) { s1 += (double)s_r1[w]; s2 += (double)s_r2[w]; }
            double mean = s1 / 49.0;
            double var = (s2 - 49.0*mean*mean) / 48.0;
            if (var < 0.0) var = 0.0;
            rowacc += sqrt(var);
        }
        __syncthreads();
    }
    if (tid == 0) atomicAdd(&g_acc[4], rowacc);
}

// ---------------------------------------------------------------- spread
__global__ void spread_kernel(const float* __restrict__ pred) {
    int b = blockIdx.x / 3, c = blockIdx.x % 3;
    const float* p = pred + (size_t)b * N_ * 3 + c;
    double s1 = 0.0, s2 = 0.0;
    for (int i = threadIdx.x; i < N_; i += 256) {
        double x = (double)p[3*i];
        s1 += x; s2 += x*x;
    }
    for (int o = 16; o; o >>= 1) {
        s1 += __shfl_xor_sync(0xFFFFFFFFu, s1, o);
        s2 += __shfl_xor_sync(0xFFFFFFFFu, s2, o);
    }
    __shared__ double sw1[8], sw2[8];
    int lane = threadIdx.x & 31, wid = threadIdx.x >> 5;
    if (lane == 0) { sw1[wid] = s1; sw2[wid] = s2; }
    __syncthreads();
    if (threadIdx.x == 0) {
        double a = 0, bb = 0;
        for (int w = 0; w < 8; w++) { a += sw1[w]; bb += sw2[w]; }
        double mean = a / (double)N_;
        double var = (bb - (double)N_ * mean * mean) / (double)(N_ - 1);
        if (var < 0.0) var = 0.0;
        atomicAdd(&g_acc[5], sqrt(var));
    }
}

// ---------------------------------------------------------------- repulsion
// NOTE: sample_idx arrives as int32 (JAX x64 disabled downcasts astype(int64)).
__global__ void repulsion_kernel(const float* __restrict__ pred,
                                 const int* __restrict__ sidx) {
    __shared__ float sp[200*3];
    int tid = threadIdx.x;
    for (int s = tid; s < 200; s += 256) {
        int b = s / 100, k = s % 100;
        int idx = sidx[k];
        if (idx < 0) idx = 0;
        if (idx >= N_) idx = N_ - 1;
        const float* src = pred + ((size_t)b * N_ + (size_t)idx) * 3;
        sp[3*s] = src[0]; sp[3*s+1] = src[1]; sp[3*s+2] = src[2];
    }
    __syncthreads();
    float sum = 0.f;
    for (int t = tid; t < 2*100*100; t += 256) {
        int b = t / 10000, rem = t % 10000, i = rem / 100, j = rem % 100;
        if (i != j) {
            const float* pi = &sp[(b*100 + i)*3];
            const float* pj = &sp[(b*100 + j)*3];
            float dx = pi[0]-pj[0], dy = pi[1]-pj[1], dz = pi[2]-pj[2];
            float dd = fmaf(dx, dx, fmaf(dy, dy, dz*dz));
            float rr = 0.01f - sqrtf(dd);
            if (rr > 0.f) sum += rr;
        }
    }
    block_add_to_acc(sum, 6);
}

// ---------------------------------------------------------------- finalize
__global__ void final_kernel(float* out) {
    double cham   = g_acc[0] / (double)(B_*N_) + g_acc[1] / (double)(B_*M_);
    double emd    = g_acc[3] / (double)(NN*3) * 0.1;
    double cov    = g_acc[2] / (double)(B_*K_) * 5.0;
    double unif   = g_acc[4] / (double)NN * 2.0;
    double sstd   = g_acc[5] / 6.0;
    double spread = 0.5 - sstd;
    spread = (spread > 0.0) ? spread * 10.0 : 0.0;
    double rep    = g_acc[6] / (double)(B_*100*100) * 5.0;
    out[0] = (float)(cham + emd + cov + unif + spread + rep);
}

// ---------------------------------------------------------------- launch
extern "C" void kernel_launch(void* const* d_in, const int* in_sizes, int n_in,
                              void* d_out, int out_size) {
    const float* pred    = (const float*)d_in[0];
    const float* gt      = (const float*)d_in[1];
    const float* partial = (const float*)d_in[2];
    const int*   sidx    = (const int*)d_in[3];
    float* out = (float*)d_out;

    init_kernel<<<32, 256>>>();
    pack_kernel<<<32, 256>>>(pred);

    // chamfer pred->gt and gt->pred, coverage partial->pred (16-way j-split)
    rowmin_kernel<<<dim3(N_/128, 16, B_), 128>>>(pred, gt,   N_, M_, M_/16, 0);
    rowmin_kernel<<<dim3(M_/128, 16, B_), 128>>>(gt,   pred, M_, N_, N_/16, 1);
    rowmin_kernel<<<dim3(K_/128, 16, B_), 128>>>(partial, pred, K_, N_, N_/16, 2);

    summin_kernel<<<(B_*N_+255)/256, 256>>>(0, B_*N_, 0, 0);
    summin_kernel<<<(B_*M_+255)/256, 256>>>(1, B_*M_, 0, 1);
    summin_kernel<<<(B_*K_+255)/256, 256>>>(2, B_*K_, 1, 2);

    emd_sort_kernel<<<6, 1024>>>(pred, gt);
    emd_diff_kernel<<<(3*NN+255)/256, 256>>>();

    uniformity_kernel<<<NN/32, 256>>>();

    spread_kernel<<<6, 256>>>(pred);
    repulsion_kernel<<<1, 256>>>(pred, sidx);

    final_kernel<<<1, 1>>>(out);
}